// round 3
// baseline (speedup 1.0000x reference)
#include <cuda_runtime.h>
#include <math.h>

#define S_LEN 512
#define B_DIM 256
#define IN_DIM 256
#define BR_DIM 128
#define H_DIM 512
#define G_DIM (4 * H_DIM)  // 2048

#define BT 32      // batch tile (lane = local batch index)
#define HT 32      // h tile (warp w owns h = ht0 + 4w .. 4w+3)
#define KC 32      // k chunk
#define NTHREADS 256
#define NCTAS 128  // (H/HT) * (B/BT) = 16 * 8

typedef unsigned long long u64;

// ---------------- device scratch (no allocations allowed) ----------------
__device__ float g_hs0[(size_t)S_LEN * B_DIM * H_DIM];  // layer-0 outputs
__device__ float g_h0[2][B_DIM * H_DIM];                // layer-0 h double buffer
__device__ float g_h1[2][B_DIM * H_DIM];                // layer-1 h double buffer
__device__ unsigned g_arrive;
__device__ volatile unsigned g_release;

// ---------------- packed f32x2 helpers ----------------
__device__ __forceinline__ u64 pack2(float lo, float hi) {
    u64 r;
    asm("mov.b64 %0, {%1, %2};" : "=l"(r) : "f"(lo), "f"(hi));
    return r;
}
__device__ __forceinline__ void unpack2(u64 v, float& lo, float& hi) {
    asm("mov.b64 {%0, %1}, %2;" : "=f"(lo), "=f"(hi) : "l"(v));
}
__device__ __forceinline__ void fma2(u64& d, u64 a, u64 b) {
    asm("fma.rn.f32x2 %0, %1, %2, %0;" : "+l"(d) : "l"(a), "l"(b));
}

__device__ __forceinline__ float fast_sigmoid(float x) {
    return 1.0f / (1.0f + __expf(-x));
}
__device__ __forceinline__ float fast_tanh(float x) {
    // 1 - 2/(e^{2x}+1); robust at +-inf
    return 1.0f - 2.0f / (__expf(2.0f * x) + 1.0f);
}

// ---------------- grid-wide sense barrier (all 128 CTAs co-resident) ----------------
__device__ __forceinline__ void gsync(unsigned gen) {
    __syncthreads();
    if (threadIdx.x == 0) {
        __threadfence();
        unsigned a = atomicAdd(&g_arrive, 1u);
        if (a == NCTAS - 1) {
            g_arrive = 0;
            __threadfence();
            g_release = gen;
        } else {
            while (g_release < gen) { }
            __threadfence();
        }
    }
    __syncthreads();
}

// ---------------- K-segment accumulation ----------------
// acc[g][p]: packed pair accumulators; thread (lane, wrp) owns
// b = bt0 + lane, h = ht0 + 4*wrp + {0,1}(p=0) / {2,3}(p=1), 4 gates.
// A: [B_DIM x ldA] row-major.  W: [Kseg x G_DIM], column = g*H + h.
__device__ __forceinline__ void accum_seg(
    u64 acc[4][2],
    const float* __restrict__ A, int ldA, int Kseg,
    const float* __restrict__ W,
    int bt0, int ht0,
    float* As /*[KC*33]*/, float* Ws /*[KC*128], [k][g][h]*/)
{
    const int tid = threadIdx.x;
    const int lane = tid & 31;
    const int wrp = tid >> 5;

    for (int kc = 0; kc < Kseg; kc += KC) {
        __syncthreads();  // protect previous chunk's readers
        // As[k][b], gmem-coalesced over k, conflict-free STS (stride 33)
        #pragma unroll
        for (int e = 0; e < (BT * KC) / NTHREADS; e++) {
            int lin = tid + NTHREADS * e;
            int k = lin & 31, b = lin >> 5;
            As[k * 33 + b] = A[(size_t)(bt0 + b) * ldA + kc + k];
        }
        // Ws[k][g][h]: direct coalesced copy, conflict-free STS
        #pragma unroll
        for (int e = 0; e < (KC * 4 * HT) / NTHREADS; e++) {
            int lin = tid + NTHREADS * e;
            int h = lin & 31, g = (lin >> 5) & 3, k = lin >> 7;
            Ws[k * 128 + g * 32 + h] = W[(size_t)(kc + k) * G_DIM + g * H_DIM + ht0 + h];
        }
        __syncthreads();
        #pragma unroll
        for (int k = 0; k < KC; k++) {
            float a = As[k * 33 + lane];       // per-lane, conflict-free
            u64 aa = pack2(a, a);
            const ulonglong2* wp =
                (const ulonglong2*)(Ws + k * 128 + 4 * wrp);  // 16B aligned
            #pragma unroll
            for (int g = 0; g < 4; g++) {
                ulonglong2 w = wp[g * 8];  // broadcast LDS.128: (w0,w1),(w2,w3)
                fma2(acc[g][0], w.x, aa);
                fma2(acc[g][1], w.y, aa);
            }
        }
    }
}

// gate epilogue: returns packed h pair, updates packed c pair
__device__ __forceinline__ u64 lstm_gates(u64 acc[4][2], int p, u64& cpack) {
    float i0, i1, f0, f1, q0, q1, o0, o1, c0, c1;
    unpack2(acc[0][p], i0, i1);
    unpack2(acc[1][p], f0, f1);
    unpack2(acc[2][p], q0, q1);
    unpack2(acc[3][p], o0, o1);
    unpack2(cpack, c0, c1);
    c0 = fast_sigmoid(f0) * c0 + fast_sigmoid(i0) * fast_tanh(q0);
    c1 = fast_sigmoid(f1) * c1 + fast_sigmoid(i1) * fast_tanh(q1);
    cpack = pack2(c0, c1);
    float h0 = fast_sigmoid(o0) * fast_tanh(c0);
    float h1 = fast_sigmoid(o1) * fast_tanh(c1);
    return pack2(h0, h1);
}

__global__ void __launch_bounds__(NTHREADS, 1) init_kernel() {
    int i = blockIdx.x * blockDim.x + threadIdx.x;
    if (i == 0) { g_arrive = 0; g_release = 0; }
    if (i < B_DIM * H_DIM) {
        g_h0[0][i] = 0.0f;
        g_h1[0][i] = 0.0f;
    }
}

// ---------------- layer 0: persistent over all 512 steps ----------------
__global__ void __launch_bounds__(NTHREADS, 1) layer0_kernel(
    const float* __restrict__ x, const float* __restrict__ br,
    const float* __restrict__ Wih, const float* __restrict__ Wbh,
    const float* __restrict__ Whh, const float* __restrict__ bias,
    float* __restrict__ out)
{
    __shared__ __align__(16) float As[KC * 33];
    __shared__ __align__(16) float Ws[KC * 128];
    const int tid = threadIdx.x;
    const int lane = tid & 31;
    const int wrp = tid >> 5;
    const int ht0 = blockIdx.x * HT;
    const int bt0 = blockIdx.y * BT;
    const int b = bt0 + lane;
    const int h0 = ht0 + 4 * wrp;
    const size_t oidx = (size_t)b * H_DIM + h0;  // 16B-aligned float4 slot

    // biases for the 4 owned h columns, per gate, as packed pairs
    u64 bias01[4], bias23[4];
    #pragma unroll
    for (int g = 0; g < 4; g++) {
        ulonglong2 bv = *(const ulonglong2*)(bias + g * H_DIM + h0);
        bias01[g] = bv.x; bias23[g] = bv.y;
    }

    u64 c01 = 0, c23 = 0;  // c-state lives in registers for all 512 steps
    u64 hv01 = 0, hv23 = 0;

    for (int t = 0; t < S_LEN; t++) {
        u64 acc[4][2];
        #pragma unroll
        for (int g = 0; g < 4; g++) { acc[g][0] = bias01[g]; acc[g][1] = bias23[g]; }

        accum_seg(acc, g_h0[t & 1], H_DIM, H_DIM, Whh, bt0, ht0, As, Ws);
        accum_seg(acc, x + (size_t)t * B_DIM * IN_DIM, IN_DIM, IN_DIM, Wih, bt0, ht0, As, Ws);
        accum_seg(acc, br + (size_t)t * B_DIM * BR_DIM, BR_DIM, BR_DIM, Wbh, bt0, ht0, As, Ws);

        hv01 = lstm_gates(acc, 0, c01);
        hv23 = lstm_gates(acc, 1, c23);

        ulonglong2 hv; hv.x = hv01; hv.y = hv23;
        *(ulonglong2*)(&g_h0[(t + 1) & 1][oidx]) = hv;
        *(ulonglong2*)(&g_hs0[(size_t)t * B_DIM * H_DIM + oidx]) = hv;

        gsync((unsigned)(t + 1));
    }

    // h_n[0], c_n[0] straight into out
    size_t base = (size_t)S_LEN * B_DIM * H_DIM;
    ulonglong2 hv; hv.x = hv01; hv.y = hv23;
    ulonglong2 cv; cv.x = c01;  cv.y = c23;
    *(ulonglong2*)(out + base + oidx) = hv;
    *(ulonglong2*)(out + base + 2 * (size_t)B_DIM * H_DIM + oidx) = cv;
}

// ---------------- layer 1: persistent over all 512 steps ----------------
__global__ void __launch_bounds__(NTHREADS, 1) layer1_kernel(
    const float* __restrict__ Wih, const float* __restrict__ Whh,
    const float* __restrict__ bias, float* __restrict__ out)
{
    __shared__ __align__(16) float As[KC * 33];
    __shared__ __align__(16) float Ws[KC * 128];
    const int tid = threadIdx.x;
    const int lane = tid & 31;
    const int wrp = tid >> 5;
    const int ht0 = blockIdx.x * HT;
    const int bt0 = blockIdx.y * BT;
    const int b = bt0 + lane;
    const int h0 = ht0 + 4 * wrp;
    const size_t oidx = (size_t)b * H_DIM + h0;

    u64 bias01[4], bias23[4];
    #pragma unroll
    for (int g = 0; g < 4; g++) {
        ulonglong2 bv = *(const ulonglong2*)(bias + g * H_DIM + h0);
        bias01[g] = bv.x; bias23[g] = bv.y;
    }

    u64 c01 = 0, c23 = 0;
    u64 hv01 = 0, hv23 = 0;

    for (int t = 0; t < S_LEN; t++) {
        u64 acc[4][2];
        #pragma unroll
        for (int g = 0; g < 4; g++) { acc[g][0] = bias01[g]; acc[g][1] = bias23[g]; }

        accum_seg(acc, g_h1[t & 1], H_DIM, H_DIM, Whh, bt0, ht0, As, Ws);
        accum_seg(acc, g_hs0 + (size_t)t * B_DIM * H_DIM, H_DIM, H_DIM, Wih, bt0, ht0, As, Ws);

        hv01 = lstm_gates(acc, 0, c01);
        hv23 = lstm_gates(acc, 1, c23);

        ulonglong2 hv; hv.x = hv01; hv.y = hv23;
        *(ulonglong2*)(&g_h1[(t + 1) & 1][oidx]) = hv;
        *(ulonglong2*)(out + (size_t)t * B_DIM * H_DIM + oidx) = hv;  // hs1

        gsync((unsigned)(S_LEN + t + 1));
    }

    size_t base = (size_t)S_LEN * B_DIM * H_DIM;
    ulonglong2 hv; hv.x = hv01; hv.y = hv23;
    ulonglong2 cv; cv.x = c01;  cv.y = c23;
    *(ulonglong2*)(out + base + 1 * (size_t)B_DIM * H_DIM + oidx) = hv;
    *(ulonglong2*)(out + base + 3 * (size_t)B_DIM * H_DIM + oidx) = cv;
}

extern "C" void kernel_launch(void* const* d_in, const int* in_sizes, int n_in,
                              void* d_out, int out_size)
{
    const float* x    = (const float*)d_in[0];  // [S, B, IN]
    const float* br   = (const float*)d_in[1];  // [S, B, BR]
    const float* Wih0 = (const float*)d_in[2];  // [IN, 4H]
    const float* Wbh0 = (const float*)d_in[3];  // [BR, 4H]
    const float* Whh0 = (const float*)d_in[4];  // [H, 4H]
    const float* b0   = (const float*)d_in[5];  // [4H]
    const float* Wih1 = (const float*)d_in[6];  // [H, 4H]
    const float* Whh1 = (const float*)d_in[7];  // [H, 4H]
    const float* b1   = (const float*)d_in[8];  // [4H]
    float* out = (float*)d_out;

    init_kernel<<<(B_DIM * H_DIM + NTHREADS - 1) / NTHREADS, NTHREADS>>>();

    dim3 grid(H_DIM / HT, B_DIM / BT);  // (16, 8) = 128 CTAs, one per SM
    layer0_kernel<<<grid, NTHREADS>>>(x, br, Wih0, Wbh0, Whh0, b0, out);
    layer1_kernel<<<grid, NTHREADS>>>(Wih1, Whh1, b1, out);
}